// round 7
// baseline (speedup 1.0000x reference)
#include <cuda_runtime.h>
#include <math.h>
#include <stdint.h>

#define B_ 4
#define N_ 2048
#define C_ 1024
#define M_TOT (B_ * N_)   // 8192
#define QMAX 11392.0f     // 89*128 = 11392; |h|<=89, |l|<=64

typedef signed char s8;

// ---------------- scratch (__device__ globals; no allocation) ----------------
__device__ __align__(128) s8 g_h_h[(size_t)M_TOT * C_],  g_h_l[(size_t)M_TOT * C_];
__device__ __align__(128) s8 g_Wq_h[C_ * C_], g_Wq_l[C_ * C_];
__device__ __align__(128) s8 g_Wk_h[C_ * C_], g_Wk_l[C_ * C_];
__device__ __align__(128) s8 g_Wv_h[C_ * C_], g_Wv_l[C_ * C_];
__device__ __align__(128) s8 g_Q_h[(size_t)M_TOT * C_],  g_Q_l[(size_t)M_TOT * C_];
__device__ __align__(128) s8 g_K_h[(size_t)M_TOT * C_],  g_K_l[(size_t)M_TOT * C_];
__device__ __align__(128) s8 g_VT_h[(size_t)C_ * M_TOT], g_VT_l[(size_t)C_ * M_TOT];
__device__ __align__(128) s8 g_P_h[(size_t)B_ * N_ * N_], g_P_l[(size_t)B_ * N_ * N_];

__device__ float g_s_h[M_TOT], g_s_Wq[C_], g_s_Wk[C_], g_s_Wv[C_];
__device__ float g_s_Q[M_TOT], g_s_K[M_TOT], g_s_VT[C_], g_s_P[B_ * N_];

__device__ __align__(128) float g_Qf[(size_t)M_TOT * C_];
__device__ __align__(128) float g_Kf[(size_t)M_TOT * C_];
__device__ __align__(128) float g_VTf[(size_t)C_ * M_TOT];

// ---------------- portable PTX helpers ----------------
__device__ __forceinline__ uint32_t smem_u32(const void* p) {
    uint32_t a;
    asm("{ .reg .u64 t; cvta.to.shared.u64 t, %1; cvt.u32.u64 %0, t; }" : "=r"(a) : "l"(p));
    return a;
}
__device__ __forceinline__ void cp_async16(uint32_t dst, const void* src) {
    asm volatile("cp.async.cg.shared.global [%0], [%1], 16;" :: "r"(dst), "l"(src) : "memory");
}
#define CP_COMMIT()  asm volatile("cp.async.commit_group;" ::: "memory")
#define CP_WAIT(n)   asm volatile("cp.async.wait_group %0;" :: "n"(n) : "memory")

__device__ __forceinline__ void ldsm_x4(uint32_t& r0, uint32_t& r1, uint32_t& r2, uint32_t& r3,
                                        uint32_t addr) {
    asm volatile("ldmatrix.sync.aligned.m8n8.x4.shared.b16 {%0,%1,%2,%3}, [%4];"
                 : "=r"(r0), "=r"(r1), "=r"(r2), "=r"(r3) : "r"(addr));
}
// int8 MMA: m16n8k32, s32 accumulate (4096 MACs per instruction)
__device__ __forceinline__ void mma_i8(int* d, const uint32_t* a, const uint32_t* b) {
    asm volatile(
        "mma.sync.aligned.m16n8k32.row.col.s32.s8.s8.s32 "
        "{%0,%1,%2,%3}, {%4,%5,%6,%7}, {%8,%9}, {%0,%1,%2,%3};"
        : "+r"(d[0]), "+r"(d[1]), "+r"(d[2]), "+r"(d[3])
        : "r"(a[0]), "r"(a[1]), "r"(a[2]), "r"(a[3]), "r"(b[0]), "r"(b[1]));
}
__device__ __forceinline__ uint32_t swz(uint32_t off) { return off ^ ((off >> 3) & 0x70); }

// ---------------- int8x2 GEMM ----------------
// out = alpha * s_a[m]*s_b[n]*128*( 128*(Ah@Bh^T) + Ah@Bl^T + Al@Bh^T ) (+bias)
// A: [M,K] int8 planes row-major (lda = K elems). B: [N,K] int8 planes (ldb).
// Block tile 128x256; K chunk = 128 int8 (128B rows); 8 warps 2x4, warp tile 64x64.
#define BM_ 128
#define BN_ 256
#define STAGES 4
#define TILE_A_BYTES 16384
#define STAGE_BYTES  49152
#define SMEM_GEMM (STAGES * STAGE_BYTES)   // 192 KB

__global__ __launch_bounds__(256, 1) void gemm_i8x2(
    const s8* __restrict__ Ah, const s8* __restrict__ Al,
    const s8* __restrict__ Bh, const s8* __restrict__ Bl,
    int lda, int ldb, long long batA, long long batB, int K,
    const float* __restrict__ sA, int batSA,
    const float* __restrict__ sB, int batSB,
    float* __restrict__ C, long long batC, int ldc,
    float alpha, const float* __restrict__ bias, int bias_mode)
{
    extern __shared__ char smem[];
    const uint32_t sbase = smem_u32(smem);
    const int tid  = threadIdx.x;
    const int wid  = tid >> 5;
    const int lane = tid & 31;
    const long long bz = blockIdx.z;
    const int m0 = blockIdx.y * BM_;
    const int n0 = blockIdx.x * BN_;

    const s8* A_h = Ah + bz * batA;
    const s8* A_l = Al + bz * batA;
    const s8* B_h = Bh + bz * batB;
    const s8* B_l = Bl + bz * batB;

    const int wm = (wid >> 2) * 64;
    const int wn = (wid & 3) * 64;

    const int nkp = K >> 7;    // K/128 chunks per pass segment
    const int NK  = 3 * nkp;   // hh (nkp) + h*l (nkp) + l*h (nkp)

    const int lrow = tid >> 3;
    const int lch  = tid & 7;

    auto load_stage = [&](int kc, int stg) {
        int p  = kc / nkp;
        int kk = kc - p * nkp;
        const s8* Asrc = (p == 2) ? A_l : A_h;
        const s8* Bsrc = (p == 1) ? B_l : B_h;
        Asrc += (size_t)m0 * lda + kk * 128;
        Bsrc += (size_t)n0 * ldb + kk * 128;
        const uint32_t sa = sbase + stg * STAGE_BYTES;
        const uint32_t sb = sa + TILE_A_BYTES;
        #pragma unroll
        for (int r = 0; r < 4; r++) {
            int row = r * 32 + lrow;
            uint32_t sw = swz(row * 128 + lch * 16);
            cp_async16(sa + sw, Asrc + (size_t)row * lda + lch * 16);
        }
        #pragma unroll
        for (int r = 0; r < 8; r++) {
            int row = r * 32 + lrow;
            uint32_t sw = swz(row * 128 + lch * 16);
            cp_async16(sb + sw, Bsrc + (size_t)row * ldb + lch * 16);
        }
        CP_COMMIT();
    };

    int acc[4][8][4];
    #pragma unroll
    for (int i = 0; i < 4; i++)
        #pragma unroll
        for (int j = 0; j < 8; j++)
            #pragma unroll
            for (int e = 0; e < 4; e++) acc[i][j][e] = 0;

    const int a_row_l = ((lane >> 3) & 1) * 8 + (lane & 7);
    const int a_col_l = ((lane >> 4) & 1) * 16;
    const int b_row_l = ((lane >> 4) & 1) * 8 + (lane & 7);
    const int b_col_l = ((lane >> 3) & 1) * 16;

    #pragma unroll
    for (int i = 0; i < STAGES - 1; i++) load_stage(i, i);

    for (int kc = 0; kc < NK; kc++) {
        int rem = NK - 1 - kc;
        if (rem >= 2)      { CP_WAIT(2); }
        else if (rem == 1) { CP_WAIT(1); }
        else               { CP_WAIT(0); }
        __syncthreads();

        if (kc + STAGES - 1 < NK) load_stage(kc + STAGES - 1, (kc + STAGES - 1) & (STAGES - 1));

        // between pass 1 (hh) and pass 2 (cross): weight hh by 128
        if (kc == nkp) {
            #pragma unroll
            for (int i = 0; i < 4; i++)
                #pragma unroll
                for (int j = 0; j < 8; j++)
                    #pragma unroll
                    for (int e = 0; e < 4; e++) acc[i][j][e] <<= 7;
        }

        const uint32_t cur_sa = sbase + (kc & (STAGES - 1)) * STAGE_BYTES;
        const uint32_t cur_sb = cur_sa + TILE_A_BYTES;

        #pragma unroll
        for (int ks = 0; ks < 4; ks++) {      // 4 k32 steps per 128B chunk
            uint32_t a[4][4], b[8][2];
            #pragma unroll
            for (int mt = 0; mt < 4; mt++) {
                uint32_t off = (uint32_t)(wm + mt * 16 + a_row_l) * 128 + ks * 32 + a_col_l;
                ldsm_x4(a[mt][0], a[mt][1], a[mt][2], a[mt][3], cur_sa + swz(off));
            }
            #pragma unroll
            for (int nt2 = 0; nt2 < 4; nt2++) {
                uint32_t off = (uint32_t)(wn + nt2 * 16 + b_row_l) * 128 + ks * 32 + b_col_l;
                uint32_t r0, r1, r2, r3;
                ldsm_x4(r0, r1, r2, r3, cur_sb + swz(off));
                b[nt2 * 2 + 0][0] = r0; b[nt2 * 2 + 0][1] = r1;
                b[nt2 * 2 + 1][0] = r2; b[nt2 * 2 + 1][1] = r3;
            }
            #pragma unroll
            for (int mt = 0; mt < 4; mt++)
                #pragma unroll
                for (int nt = 0; nt < 8; nt++)
                    mma_i8(acc[mt][nt], a[mt], b[nt]);
        }
    }

    // ---------------- epilogue ----------------
    const int erow = lane >> 2;
    const int ecol = (lane & 3) * 2;
    const float kfac = 128.0f * alpha;
    const float* sAp = sA + (size_t)bz * batSA;
    const float* sBp = sB + (size_t)bz * batSB;

    #pragma unroll
    for (int mt = 0; mt < 4; mt++) {
        #pragma unroll
        for (int h = 0; h < 2; h++) {
            const int gm = m0 + wm + mt * 16 + h * 8 + erow;
            const float sam = sAp[gm] * kfac;
            const float brow = (bias_mode == 2) ? bias[gm] : 0.f;
            #pragma unroll
            for (int nt = 0; nt < 8; nt++) {
                const int gn = n0 + wn + nt * 8 + ecol;
                float x0 = (float)acc[mt][nt][h * 2 + 0] * (sam * sBp[gn]);
                float x1 = (float)acc[mt][nt][h * 2 + 1] * (sam * sBp[gn + 1]);
                if (bias_mode == 1) { x0 += bias[gn]; x1 += bias[gn + 1]; }
                else if (bias_mode == 2) { x0 += brow; x1 += brow; }
                float2 v; v.x = x0; v.y = x1;
                *(float2*)(C + bz * batC + (size_t)gm * ldc + gn) = v;
            }
        }
    }
}

// ---------------- row quantization: fp32 row -> (h,l) int8 planes + scale ----------------
__global__ __launch_bounds__(256) void rowquant(
    const float* __restrict__ x, s8* __restrict__ qh, s8* __restrict__ ql,
    float* __restrict__ s, int klen)
{
    const size_t row = blockIdx.x;
    const float* xr = x + row * (size_t)klen;
    const int tid = threadIdx.x;
    const int lane = tid & 31;
    const int warp = tid >> 5;
    const int nv = klen >> 10;   // float4s per thread (klen/(256*4))

    float4 v[8];
    float m = 0.f;
    for (int i = 0; i < nv; i++) {
        v[i] = ((const float4*)xr)[tid + i * 256];
        m = fmaxf(m, fmaxf(fmaxf(fabsf(v[i].x), fabsf(v[i].y)),
                           fmaxf(fabsf(v[i].z), fabsf(v[i].w))));
    }
    __shared__ float red[8];
    #pragma unroll
    for (int off = 16; off > 0; off >>= 1)
        m = fmaxf(m, __shfl_xor_sync(0xffffffffu, m, off));
    if (lane == 0) red[warp] = m;
    __syncthreads();
    float mx = red[0];
    #pragma unroll
    for (int w = 1; w < 8; w++) mx = fmaxf(mx, red[w]);
    mx = fmaxf(mx, 1e-20f);

    if (tid == 0) s[row] = mx / QMAX;
    const float inv = QMAX / mx;

    for (int i = 0; i < nv; i++) {
        float vv[4] = {v[i].x, v[i].y, v[i].z, v[i].w};
        union { uint32_t u; s8 c[4]; } ph, pl;
        #pragma unroll
        for (int e = 0; e < 4; e++) {
            int q = __float2int_rn(vv[e] * inv);
            int hh = (q + ((q >= 0) ? 64 : -64)) / 128;
            int ll = q - (hh << 7);
            ph.c[e] = (s8)hh;
            pl.c[e] = (s8)ll;
        }
        size_t idx = row * (size_t)klen + (tid + i * 256) * 4;
        *(uint32_t*)(qh + idx) = ph.u;
        *(uint32_t*)(ql + idx) = pl.u;
    }
}

// ---------------- softmax (rows of 2048) + int8 quantization of P ----------------
__global__ __launch_bounds__(256) void softmax_quant(
    float* __restrict__ P, s8* __restrict__ Ph, s8* __restrict__ Pl,
    float* __restrict__ sP)
{
    const size_t row = blockIdx.x;
    float* p = P + row * (size_t)N_;
    s8* ph = Ph + row * (size_t)N_;
    s8* pl = Pl + row * (size_t)N_;
    const int tid = threadIdx.x;
    const int lane = tid & 31;
    const int warp = tid >> 5;

    float vals[8];
    float m = -INFINITY;
    #pragma unroll
    for (int i = 0; i < 8; i++) {
        vals[i] = p[tid + i * 256];
        m = fmaxf(m, vals[i]);
    }
    __shared__ float redmax[8], redsum[8];
    #pragma unroll
    for (int off = 16; off > 0; off >>= 1)
        m = fmaxf(m, __shfl_xor_sync(0xffffffffu, m, off));
    if (lane == 0) redmax[warp] = m;
    __syncthreads();
    float rowmax = redmax[0];
    #pragma unroll
    for (int w = 1; w < 8; w++) rowmax = fmaxf(rowmax, redmax[w]);

    float sum = 0.f;
    #pragma unroll
    for (int i = 0; i < 8; i++) {
        vals[i] = expf(vals[i] - rowmax);
        sum += vals[i];
    }
    #pragma unroll
    for (int off = 16; off > 0; off >>= 1)
        sum += __shfl_xor_sync(0xffffffffu, sum, off);
    if (lane == 0) redsum[warp] = sum;
    __syncthreads();
    float total = 0.f;
    #pragma unroll
    for (int w = 0; w < 8; w++) total += redsum[w];
    float inv = 1.f / total;

    if (tid == 0) sP[row] = inv / QMAX;   // p_max = inv (max val = 1)

    #pragma unroll
    for (int i = 0; i < 8; i++) {
        float pv = vals[i] * inv;
        p[tid + i * 256] = pv;
        int q = __float2int_rn(vals[i] * QMAX);   // q = pv / s, vals in [0,1]
        int hh = (q + 64) >> 7;
        int ll = q - (hh << 7);
        ph[tid + i * 256] = (s8)hh;
        pl[tid + i * 256] = (s8)ll;
    }
}

// ---------------- launch ----------------
extern "C" void kernel_launch(void* const* d_in, const int* in_sizes, int n_in,
                              void* d_out, int out_size)
{
    const float* h  = (const float*)d_in[0];
    const float* Wq = (const float*)d_in[1];
    const float* bq = (const float*)d_in[2];
    const float* Wk = (const float*)d_in[3];
    const float* bk = (const float*)d_in[4];
    const float* Wv = (const float*)d_in[5];
    const float* bv = (const float*)d_in[6];

    float* out  = (float*)d_out;                 // [B,N,C]
    float* attn = out + (size_t)B_ * N_ * C_;    // [B,N,N]

    s8 *h_h, *h_l, *Wq_h, *Wq_l, *Wk_h, *Wk_l, *Wv_h, *Wv_l;
    s8 *Q_h, *Q_l, *K_h, *K_l, *VT_h, *VT_l, *P_h, *P_l;
    float *s_h, *s_Wq, *s_Wk, *s_Wv, *s_Q, *s_K, *s_VT, *s_P;
    float *Qf, *Kf, *VTf;
    cudaGetSymbolAddress((void**)&h_h, g_h_h);   cudaGetSymbolAddress((void**)&h_l, g_h_l);
    cudaGetSymbolAddress((void**)&Wq_h, g_Wq_h); cudaGetSymbolAddress((void**)&Wq_l, g_Wq_l);
    cudaGetSymbolAddress((void**)&Wk_h, g_Wk_h); cudaGetSymbolAddress((void**)&Wk_l, g_Wk_l);
    cudaGetSymbolAddress((void**)&Wv_h, g_Wv_h); cudaGetSymbolAddress((void**)&Wv_l, g_Wv_l);
    cudaGetSymbolAddress((void**)&Q_h, g_Q_h);   cudaGetSymbolAddress((void**)&Q_l, g_Q_l);
    cudaGetSymbolAddress((void**)&K_h, g_K_h);   cudaGetSymbolAddress((void**)&K_l, g_K_l);
    cudaGetSymbolAddress((void**)&VT_h, g_VT_h); cudaGetSymbolAddress((void**)&VT_l, g_VT_l);
    cudaGetSymbolAddress((void**)&P_h, g_P_h);   cudaGetSymbolAddress((void**)&P_l, g_P_l);
    cudaGetSymbolAddress((void**)&s_h, g_s_h);   cudaGetSymbolAddress((void**)&s_Wq, g_s_Wq);
    cudaGetSymbolAddress((void**)&s_Wk, g_s_Wk); cudaGetSymbolAddress((void**)&s_Wv, g_s_Wv);
    cudaGetSymbolAddress((void**)&s_Q, g_s_Q);   cudaGetSymbolAddress((void**)&s_K, g_s_K);
    cudaGetSymbolAddress((void**)&s_VT, g_s_VT); cudaGetSymbolAddress((void**)&s_P, g_s_P);
    cudaGetSymbolAddress((void**)&Qf, g_Qf);     cudaGetSymbolAddress((void**)&Kf, g_Kf);
    cudaGetSymbolAddress((void**)&VTf, g_VTf);

    cudaFuncSetAttribute(gemm_i8x2, cudaFuncAttributeMaxDynamicSharedMemorySize, SMEM_GEMM);

    // 1) quantize inputs
    rowquant<<<M_TOT, 256>>>(h, h_h, h_l, s_h, C_);
    rowquant<<<C_, 256>>>(Wq, Wq_h, Wq_l, s_Wq, C_);
    rowquant<<<C_, 256>>>(Wk, Wk_h, Wk_l, s_Wk, C_);
    rowquant<<<C_, 256>>>(Wv, Wv_h, Wv_l, s_Wv, C_);

    dim3 blk(256);

    // 2) Q = h @ Wq^T + bq ; K = h @ Wk^T + bk   (fp32 scratch)
    {
        dim3 g(C_ / BN_, M_TOT / BM_, 1);
        gemm_i8x2<<<g, blk, SMEM_GEMM>>>(h_h, h_l, Wq_h, Wq_l, C_, C_, 0, 0, C_,
                                         s_h, 0, s_Wq, 0, Qf, 0, C_, 1.0f, bq, 1);
        gemm_i8x2<<<g, blk, SMEM_GEMM>>>(h_h, h_l, Wk_h, Wk_l, C_, C_, 0, 0, C_,
                                         s_h, 0, s_Wk, 0, Kf, 0, C_, 1.0f, bk, 1);
    }
    // 3) V^T = Wv @ h^T + bv (row bias) -> [C_, M_TOT] fp32 scratch
    {
        dim3 g(M_TOT / BN_, C_ / BM_, 1);
        gemm_i8x2<<<g, blk, SMEM_GEMM>>>(Wv_h, Wv_l, h_h, h_l, C_, C_, 0, 0, C_,
                                         s_Wv, 0, s_h, 0, VTf, 0, M_TOT, 1.0f, bv, 2);
    }
    // 4) quantize Q, K, V^T
    rowquant<<<M_TOT, 256>>>(Qf, Q_h, Q_l, s_Q, C_);
    rowquant<<<M_TOT, 256>>>(Kf, K_h, K_l, s_K, C_);
    rowquant<<<C_, 256>>>(VTf, VT_h, VT_l, s_VT, M_TOT);

    // 5) scores = (Q @ K^T) / 32 -> fp32 attn (per batch)
    {
        dim3 g(N_ / BN_, N_ / BM_, B_);
        gemm_i8x2<<<g, blk, SMEM_GEMM>>>(
            Q_h, Q_l, K_h, K_l, C_, C_,
            (long long)N_ * C_, (long long)N_ * C_, C_,
            s_Q, N_, s_K, N_,
            attn, (long long)N_ * N_, N_, 1.0f / 32.0f, nullptr, 0);
    }
    // 6) softmax (in place) + quantize P
    softmax_quant<<<B_ * N_, 256>>>(attn, P_h, P_l, s_P);

    // 7) out = P @ (V^T)^T (per batch, K = 2048)
    {
        dim3 g(C_ / BN_, N_ / BM_, B_);
        gemm_i8x2<<<g, blk, SMEM_GEMM>>>(
            P_h, P_l, VT_h, VT_l, N_, M_TOT,
            (long long)N_ * N_, (long long)N_,
            N_,
            s_P, N_, s_VT, 0,
            out, (long long)N_ * C_, C_, 1.0f, nullptr, 0);
    }
}

// round 8
// speedup vs baseline: 7.1129x; 7.1129x over previous
#include <cuda_runtime.h>
#include <cuda_fp16.h>
#include <math.h>
#include <stdint.h>

#define B_ 4
#define N_ 2048
#define C_ 1024
#define M_TOT (B_ * N_)   // 8192

// ---------------- scratch (__device__ globals; no allocation) ----------------
__device__ __align__(128) __half g_hh[(size_t)M_TOT * C_];
__device__ __align__(128) __half g_Wqh[C_ * C_], g_Wkh[C_ * C_], g_Wvh[C_ * C_];
__device__ __align__(128) __half g_Q[(size_t)M_TOT * C_];
__device__ __align__(128) __half g_K[(size_t)M_TOT * C_];
__device__ __align__(128) __half g_VT[(size_t)C_ * M_TOT];   // [C_, M_TOT]
__device__ __align__(128) __half g_P[(size_t)B_ * N_ * N_];

// ---------------- portable PTX helpers (base-target safe) ----------------
__device__ __forceinline__ uint32_t smem_u32(const void* p) {
    uint32_t a;
    asm("{ .reg .u64 t; cvta.to.shared.u64 t, %1; cvt.u32.u64 %0, t; }" : "=r"(a) : "l"(p));
    return a;
}
__device__ __forceinline__ void cp_async16(uint32_t dst, const void* src) {
    asm volatile("cp.async.cg.shared.global [%0], [%1], 16;" :: "r"(dst), "l"(src) : "memory");
}
#define CP_COMMIT()  asm volatile("cp.async.commit_group;" ::: "memory")
#define CP_WAIT(n)   asm volatile("cp.async.wait_group %0;" :: "n"(n) : "memory")

__device__ __forceinline__ void ldsm_x4(uint32_t& r0, uint32_t& r1, uint32_t& r2, uint32_t& r3,
                                        uint32_t addr) {
    asm volatile("ldmatrix.sync.aligned.m8n8.x4.shared.b16 {%0,%1,%2,%3}, [%4];"
                 : "=r"(r0), "=r"(r1), "=r"(r2), "=r"(r3) : "r"(addr));
}
__device__ __forceinline__ void mma16816(float* d, const uint32_t* a, const uint32_t* b) {
    asm volatile(
        "mma.sync.aligned.m16n8k16.row.col.f32.f16.f16.f32 "
        "{%0,%1,%2,%3}, {%4,%5,%6,%7}, {%8,%9}, {%0,%1,%2,%3};"
        : "+f"(d[0]), "+f"(d[1]), "+f"(d[2]), "+f"(d[3])
        : "r"(a[0]), "r"(a[1]), "r"(a[2]), "r"(a[3]), "r"(b[0]), "r"(b[1]));
}
__device__ __forceinline__ uint32_t swz(uint32_t off) { return off ^ ((off >> 3) & 0x70); }

// ---------------- fp16 single-pass HMMA GEMM: D = alpha*(A @ B^T) (+bias) ----------------
// A: [M,K] fp16 row-major (lda). B: [N,K] fp16 row-major (ldb). BK=64 (128B rows).
// Block tile 128x256; 8 warps 2(m) x 4(n), warp tile 64x64.
// Output fp32 (Cf) or fp16 (Ch). bias_mode: 0 none, 1 per-col, 2 per-row.
#define BM_ 128
#define BN_ 256
#define STAGES 3
#define TILE_A_BYTES 16384         // 128 rows * 128 B
#define STAGE_BYTES  49152
#define SMEM_GEMM (STAGES * STAGE_BYTES)   // 144 KB

__global__ __launch_bounds__(256, 1) void gemm_fp16(
    const __half* __restrict__ A, const __half* __restrict__ Bm,
    int lda, int ldb, long long batA, long long batB, int K,
    float* __restrict__ Cf, long long batCf, int ldc,
    __half* __restrict__ Ch, long long batCh,
    float alpha, const float* __restrict__ bias, int bias_mode)
{
    extern __shared__ char smem[];
    const uint32_t sbase = smem_u32(smem);
    const int tid  = threadIdx.x;
    const int wid  = tid >> 5;
    const int lane = tid & 31;
    const long long bz = blockIdx.z;
    const int m0 = blockIdx.y * BM_;
    const int n0 = blockIdx.x * BN_;

    const __half* Ap = A + bz * batA;
    const __half* Bp = Bm + bz * batB;

    const int wm = (wid >> 2) * 64;
    const int wn = (wid & 3) * 64;

    const int NK = K >> 6;     // K/64 chunks

    const int lrow = tid >> 3;
    const int lch  = tid & 7;

    auto load_stage = [&](int kc, int s) {
        const __half* Asrc = Ap + (size_t)m0 * lda + kc * 64;
        const __half* Bsrc = Bp + (size_t)n0 * ldb + kc * 64;
        const uint32_t sa = sbase + s * STAGE_BYTES;
        const uint32_t sb = sa + TILE_A_BYTES;
        #pragma unroll
        for (int r = 0; r < 4; r++) {
            int row = r * 32 + lrow;
            uint32_t sw = swz(row * 128 + lch * 16);
            cp_async16(sa + sw, Asrc + (size_t)row * lda + lch * 8);
        }
        #pragma unroll
        for (int r = 0; r < 8; r++) {
            int row = r * 32 + lrow;
            uint32_t sw = swz(row * 128 + lch * 16);
            cp_async16(sb + sw, Bsrc + (size_t)row * ldb + lch * 8);
        }
        CP_COMMIT();
    };

    float acc[4][8][4];
    #pragma unroll
    for (int i = 0; i < 4; i++)
        #pragma unroll
        for (int j = 0; j < 8; j++)
            #pragma unroll
            for (int e = 0; e < 4; e++) acc[i][j][e] = 0.f;

    const int a_row_l = ((lane >> 3) & 1) * 8 + (lane & 7);
    const int a_col_l = ((lane >> 4) & 1) * 16;
    const int b_row_l = ((lane >> 4) & 1) * 8 + (lane & 7);
    const int b_col_l = ((lane >> 3) & 1) * 16;

    #pragma unroll
    for (int i = 0; i < STAGES; i++)
        if (i < NK) load_stage(i, i);

    int s = 0;
    for (int kc = 0; kc < NK; kc++) {
        int rem = NK - 1 - kc;
        if (rem >= 2)      { CP_WAIT(2); }
        else if (rem == 1) { CP_WAIT(1); }
        else               { CP_WAIT(0); }
        __syncthreads();

        const uint32_t cur_sa = sbase + s * STAGE_BYTES;
        const uint32_t cur_sb = cur_sa + TILE_A_BYTES;

        #pragma unroll
        for (int k16 = 0; k16 < 4; k16++) {
            uint32_t a[4][4], b[8][2];
            #pragma unroll
            for (int mt = 0; mt < 4; mt++) {
                uint32_t off = (uint32_t)(wm + mt * 16 + a_row_l) * 128 + k16 * 32 + a_col_l;
                ldsm_x4(a[mt][0], a[mt][1], a[mt][2], a[mt][3], cur_sa + swz(off));
            }
            #pragma unroll
            for (int nt2 = 0; nt2 < 4; nt2++) {
                uint32_t off = (uint32_t)(wn + nt2 * 16 + b_row_l) * 128 + k16 * 32 + b_col_l;
                uint32_t r0, r1, r2, r3;
                ldsm_x4(r0, r1, r2, r3, cur_sb + swz(off));
                b[nt2 * 2 + 0][0] = r0; b[nt2 * 2 + 0][1] = r1;
                b[nt2 * 2 + 1][0] = r2; b[nt2 * 2 + 1][1] = r3;
            }
            #pragma unroll
            for (int mt = 0; mt < 4; mt++)
                #pragma unroll
                for (int nt = 0; nt < 8; nt++)
                    mma16816(acc[mt][nt], a[mt], b[nt]);
        }

        __syncthreads();
        if (kc + STAGES < NK) load_stage(kc + STAGES, s);
        s++;
        if (s == STAGES) s = 0;
    }

    // ---------------- epilogue ----------------
    const int erow = lane >> 2;
    const int ecol = (lane & 3) * 2;

    #pragma unroll
    for (int mt = 0; mt < 4; mt++) {
        #pragma unroll
        for (int h = 0; h < 2; h++) {
            const int gm = m0 + wm + mt * 16 + h * 8 + erow;
            float brow = (bias_mode == 2) ? bias[gm] : 0.f;
            #pragma unroll
            for (int nt = 0; nt < 8; nt++) {
                const int gn = n0 + wn + nt * 8 + ecol;
                float x0 = acc[mt][nt][h * 2 + 0] * alpha;
                float x1 = acc[mt][nt][h * 2 + 1] * alpha;
                if (bias_mode == 1) { x0 += bias[gn]; x1 += bias[gn + 1]; }
                else if (bias_mode == 2) { x0 += brow; x1 += brow; }
                if (Cf) {
                    float2 v; v.x = x0; v.y = x1;
                    *(float2*)(Cf + bz * batCf + (size_t)gm * ldc + gn) = v;
                } else {
                    __half2 hv = __floats2half2_rn(x0, x1);
                    *(__half2*)(Ch + bz * batCh + (size_t)gm * ldc + gn) = hv;
                }
            }
        }
    }
}

// ---------------- elementwise kernels ----------------
__global__ __launch_bounds__(256) void cast_fp16(
    const float* __restrict__ x, __half* __restrict__ y, size_t n4)
{
    size_t i = ((size_t)blockIdx.x * blockDim.x + threadIdx.x);
    if (i >= n4) return;
    float4 v = *(const float4*)(x + i * 4);
    __half2 h0 = __floats2half2_rn(v.x, v.y);
    __half2 h1 = __floats2half2_rn(v.z, v.w);
    uint2 u;
    u.x = *(uint32_t*)&h0;
    u.y = *(uint32_t*)&h1;
    *(uint2*)(y + i * 4) = u;
}

// softmax over rows of 2048 fp32, in-place, plus fp16 copy.
__global__ __launch_bounds__(256) void softmax_h(
    float* __restrict__ P, __half* __restrict__ Ph)
{
    const size_t row = blockIdx.x;
    float* p = P + row * (size_t)N_;
    __half* ph = Ph + row * (size_t)N_;
    const int tid = threadIdx.x;
    const int lane = tid & 31;
    const int warp = tid >> 5;

    float vals[8];
    float m = -INFINITY;
    #pragma unroll
    for (int i = 0; i < 8; i++) {
        vals[i] = p[tid + i * 256];
        m = fmaxf(m, vals[i]);
    }
    __shared__ float redmax[8], redsum[8];
    #pragma unroll
    for (int off = 16; off > 0; off >>= 1)
        m = fmaxf(m, __shfl_xor_sync(0xffffffffu, m, off));
    if (lane == 0) redmax[warp] = m;
    __syncthreads();
    float rowmax = redmax[0];
    #pragma unroll
    for (int w = 1; w < 8; w++) rowmax = fmaxf(rowmax, redmax[w]);

    float sum = 0.f;
    #pragma unroll
    for (int i = 0; i < 8; i++) {
        vals[i] = expf(vals[i] - rowmax);
        sum += vals[i];
    }
    #pragma unroll
    for (int off = 16; off > 0; off >>= 1)
        sum += __shfl_xor_sync(0xffffffffu, sum, off);
    if (lane == 0) redsum[warp] = sum;
    __syncthreads();
    float total = 0.f;
    #pragma unroll
    for (int w = 0; w < 8; w++) total += redsum[w];
    float inv = 1.f / total;

    #pragma unroll
    for (int i = 0; i < 8; i++) {
        float v = vals[i] * inv;
        p[tid + i * 256] = v;
        ph[tid + i * 256] = __float2half(v);
    }
}

// ---------------- launch ----------------
extern "C" void kernel_launch(void* const* d_in, const int* in_sizes, int n_in,
                              void* d_out, int out_size)
{
    const float* h  = (const float*)d_in[0];
    const float* Wq = (const float*)d_in[1];
    const float* bq = (const float*)d_in[2];
    const float* Wk = (const float*)d_in[3];
    const float* bk = (const float*)d_in[4];
    const float* Wv = (const float*)d_in[5];
    const float* bv = (const float*)d_in[6];

    float* out  = (float*)d_out;                 // [B,N,C]
    float* attn = out + (size_t)B_ * N_ * C_;    // [B,N,N]

    __half *hh, *Wqh, *Wkh, *Wvh, *Q, *K, *VT, *P;
    cudaGetSymbolAddress((void**)&hh, g_hh);
    cudaGetSymbolAddress((void**)&Wqh, g_Wqh);
    cudaGetSymbolAddress((void**)&Wkh, g_Wkh);
    cudaGetSymbolAddress((void**)&Wvh, g_Wvh);
    cudaGetSymbolAddress((void**)&Q, g_Q);
    cudaGetSymbolAddress((void**)&K, g_K);
    cudaGetSymbolAddress((void**)&VT, g_VT);
    cudaGetSymbolAddress((void**)&P, g_P);

    cudaFuncSetAttribute(gemm_fp16, cudaFuncAttributeMaxDynamicSharedMemorySize, SMEM_GEMM);

    // 1) casts to fp16
    {
        size_t nh4 = (size_t)M_TOT * C_ / 4;
        cast_fp16<<<(unsigned)(nh4 / 256), 256>>>(h, hh, nh4);
        size_t nw4 = (size_t)C_ * C_ / 4;
        cast_fp16<<<(unsigned)(nw4 / 256), 256>>>(Wq, Wqh, nw4);
        cast_fp16<<<(unsigned)(nw4 / 256), 256>>>(Wk, Wkh, nw4);
        cast_fp16<<<(unsigned)(nw4 / 256), 256>>>(Wv, Wvh, nw4);
    }

    dim3 blk(256);

    // 2) Q = h @ Wq^T + bq ; K = h @ Wk^T + bk  -> fp16
    {
        dim3 g(C_ / BN_, M_TOT / BM_, 1);
        gemm_fp16<<<g, blk, SMEM_GEMM>>>(hh, Wqh, C_, C_, 0, 0, C_,
                                         nullptr, 0, C_, Q, 0, 1.0f, bq, 1);
        gemm_fp16<<<g, blk, SMEM_GEMM>>>(hh, Wkh, C_, C_, 0, 0, C_,
                                         nullptr, 0, C_, K, 0, 1.0f, bk, 1);
    }
    // 3) V^T = Wv @ h^T + bv (row bias) -> fp16 [C_, M_TOT]
    {
        dim3 g(M_TOT / BN_, C_ / BM_, 1);
        gemm_fp16<<<g, blk, SMEM_GEMM>>>(Wvh, hh, C_, C_, 0, 0, C_,
                                         nullptr, 0, M_TOT, VT, 0, 1.0f, bv, 2);
    }
    // 4) scores = (Q @ K^T) / 32 -> fp32 attn (per batch)
    {
        dim3 g(N_ / BN_, N_ / BM_, B_);
        gemm_fp16<<<g, blk, SMEM_GEMM>>>(
            Q, K, C_, C_,
            (long long)N_ * C_, (long long)N_ * C_, C_,
            attn, (long long)N_ * N_, N_,
            nullptr, 0, 1.0f / 32.0f, nullptr, 0);
    }
    // 5) softmax (in place) + fp16 copy
    softmax_h<<<B_ * N_, 256>>>(attn, P);

    // 6) out = P @ (V^T)^T (per batch: M=2048, N=1024, K=2048)
    {
        dim3 g(C_ / BN_, N_ / BM_, B_);
        gemm_fp16<<<g, blk, SMEM_GEMM>>>(
            P, VT, N_, M_TOT,
            (long long)N_ * N_, (long long)N_, N_,
            out, (long long)N_ * C_, C_,
            nullptr, 0, 1.0f, nullptr, 0);
    }
}